// round 3
// baseline (speedup 1.0000x reference)
#include <cuda_runtime.h>
#include <cstdint>

#define BATCH 16
#define NPT 2048
#define DIM 64
#define NMAT 32          // 2 * BATCH  (0..15 = x/gts, 16..31 = z)
#define ECAP 196608      // per-instance filtered-edge capacity
#define T_FILT 88.0f     // d^2 threshold (expected ~55K edges/instance)

typedef unsigned long long u64;

// Scratch (allocation-free rule: __device__ globals)
__device__ float g_D[(size_t)NMAT * NPT * NPT];   // 512 MB squared distances
__device__ float g_sq[NMAT * NPT];
__device__ u64   g_elist[NMAT][ECAP];             // filtered edges (d2,i,j) packed
__device__ int   g_ecnt[NMAT];
__device__ int   g_ovf[NMAT];
__device__ int2  g_eroot[NMAT][NPT];              // MST edge recorded at hooked-root slot
__device__ float g_partial[NMAT];

// ---------------------------------------------------------------------------
// 1. squared norms (+ reset per-call counters)
// ---------------------------------------------------------------------------
__global__ void norms_kernel(const float* __restrict__ gts, const float* __restrict__ z) {
    int row = blockIdx.x * blockDim.x + threadIdx.x;
    if (blockIdx.x == 0 && threadIdx.x < NMAT) {
        g_ecnt[threadIdx.x] = 0;
        g_ovf[threadIdx.x] = 0;
    }
    if (row >= NMAT * NPT) return;
    const float* P = (row < BATCH * NPT) ? gts : z;
    int r = (row < BATCH * NPT) ? row : row - BATCH * NPT;
    const float4* p = (const float4*)(P + (size_t)r * DIM);
    float s = 0.f;
#pragma unroll
    for (int k = 0; k < DIM / 4; k++) {
        float4 v = p[k];
        s += v.x * v.x + v.y * v.y + v.z * v.z + v.w * v.w;
    }
    g_sq[row] = s;
}

// ---------------------------------------------------------------------------
// 2. squared distances D2 = max(sq_i + sq_j - 2*dot, 0); upper-triangle tiles,
//    transposed stores for symmetry, FUSED edge filter (d2 < T, i < j).
// ---------------------------------------------------------------------------
#define KS 16
__global__ void __launch_bounds__(256) dist_kernel(const float* __restrict__ gts,
                                                   const float* __restrict__ z) {
    int bi = blockIdx.y, bj = blockIdx.x;
    if (bj < bi) return;
    int bm = blockIdx.z;
    const float* P = (bm < BATCH) ? gts + (size_t)bm * NPT * DIM
                                  : z + (size_t)(bm - BATCH) * NPT * DIM;
    int i0 = bi * 128, j0 = bj * 128;
    int tid = threadIdx.x;
    int tx = tid & 15;
    int ty = tid >> 4;
    int lane = tid & 31;

    __shared__ float As[KS][132];
    __shared__ float Bs[KS][132];

    float acc[8][8] = {};

    for (int ks = 0; ks < DIM; ks += KS) {
        __syncthreads();
#pragma unroll
        for (int t = 0; t < 2; t++) {
            int idx = tid + t * 256;
            int i = idx >> 2;
            int kk = (idx & 3) * 4;
            float4 va = *(const float4*)(P + (size_t)(i0 + i) * DIM + ks + kk);
            As[kk + 0][i] = va.x; As[kk + 1][i] = va.y;
            As[kk + 2][i] = va.z; As[kk + 3][i] = va.w;
            float4 vb = *(const float4*)(P + (size_t)(j0 + i) * DIM + ks + kk);
            Bs[kk + 0][i] = vb.x; Bs[kk + 1][i] = vb.y;
            Bs[kk + 2][i] = vb.z; Bs[kk + 3][i] = vb.w;
        }
        __syncthreads();
#pragma unroll
        for (int k = 0; k < KS; k++) {
            float a[8], b[8];
            *(float4*)(a)     = *(const float4*)&As[k][ty * 8];
            *(float4*)(a + 4) = *(const float4*)&As[k][ty * 8 + 4];
            *(float4*)(b)     = *(const float4*)&Bs[k][tx * 8];
            *(float4*)(b + 4) = *(const float4*)&Bs[k][tx * 8 + 4];
#pragma unroll
            for (int r = 0; r < 8; r++)
#pragma unroll
                for (int c = 0; c < 8; c++)
                    acc[r][c] += a[r] * b[c];
        }
    }

    const float* sqb = g_sq + bm * NPT;
    float sqi[8], sqj[8];
#pragma unroll
    for (int r = 0; r < 8; r++) sqi[r] = sqb[i0 + ty * 8 + r];
#pragma unroll
    for (int c = 0; c < 8; c++) sqj[c] = sqb[j0 + tx * 8 + c];

#pragma unroll
    for (int r = 0; r < 8; r++)
#pragma unroll
        for (int c = 0; c < 8; c++)
            acc[r][c] = fmaxf(sqi[r] + sqj[c] - 2.f * acc[r][c], 0.f);

    float* Dm = g_D + (size_t)bm * NPT * NPT;
#pragma unroll
    for (int r = 0; r < 8; r++) {
        int gi = i0 + ty * 8 + r;
        float4 o0 = {acc[r][0], acc[r][1], acc[r][2], acc[r][3]};
        float4 o1 = {acc[r][4], acc[r][5], acc[r][6], acc[r][7]};
        *(float4*)&Dm[(size_t)gi * NPT + j0 + tx * 8]     = o0;
        *(float4*)&Dm[(size_t)gi * NPT + j0 + tx * 8 + 4] = o1;
    }
    if (bi != bj) {
#pragma unroll
        for (int c = 0; c < 8; c++) {
            int gj = j0 + tx * 8 + c;
            float4 o0 = {acc[0][c], acc[1][c], acc[2][c], acc[3][c]};
            float4 o1 = {acc[4][c], acc[5][c], acc[6][c], acc[7][c]};
            *(float4*)&Dm[(size_t)gj * NPT + i0 + ty * 8]     = o0;
            *(float4*)&Dm[(size_t)gj * NPT + i0 + ty * 8 + 4] = o1;
        }
    }

    // ---- fused edge filter: append (d2, i, j) with d2 < T and i < j ----
    unsigned nl = 0;
#pragma unroll
    for (int r = 0; r < 8; r++) {
        int gi = i0 + ty * 8 + r;
#pragma unroll
        for (int c = 0; c < 8; c++) {
            int gj = j0 + tx * 8 + c;
            if (gi < gj && acc[r][c] < T_FILT) nl++;
        }
    }
    unsigned pre = nl;
#pragma unroll
    for (int o = 1; o < 32; o <<= 1) {
        unsigned v = __shfl_up_sync(0xFFFFFFFFu, pre, o);
        if (lane >= (int)o) pre += v;
    }
    unsigned wtot = __shfl_sync(0xFFFFFFFFu, pre, 31);
    unsigned ex = pre - nl;
    if (wtot) {
        unsigned base = 0;
        if (lane == 31) base = (unsigned)atomicAdd(&g_ecnt[bm], (int)wtot);
        base = __shfl_sync(0xFFFFFFFFu, base, 31);
        if (base + wtot <= (unsigned)ECAP) {
            if (nl) {
                unsigned o = base + ex;
#pragma unroll
                for (int r = 0; r < 8; r++) {
                    int gi = i0 + ty * 8 + r;
#pragma unroll
                    for (int c = 0; c < 8; c++) {
                        int gj = j0 + tx * 8 + c;
                        if (gi < gj && acc[r][c] < T_FILT) {
                            g_elist[bm][o++] =
                                ((u64)__float_as_uint(acc[r][c]) << 22) |
                                ((unsigned)gi << 11) | (unsigned)gj;
                        }
                    }
                }
            }
        } else if (lane == 0) {
            g_ovf[bm] = 1;
        }
    }
}

// ---------------------------------------------------------------------------
// 3. Borůvka MST. One block per instance. Sparse phase over filtered edges
//    (all edges < T => every accepted edge is a true MST edge). Exact
//    full-matrix fallback phase guarantees completion for any input.
//    Keys (d2bits<<22 | lo<<11 | hi) give a strict total order => the only
//    hooking cycles are mutual pairs (fixed by index). Edge recorded at the
//    hooked root's slot => deterministic output layout.
// ---------------------------------------------------------------------------
__global__ void __launch_bounds__(256) boruvka_kernel() {
    __shared__ int comp[NPT];     // 8 KB
    __shared__ int parent[NPT];   // 8 KB
    __shared__ u64 best[NPT];     // 16 KB
    __shared__ int s_rec;

    int bm = blockIdx.x;
    int tid = threadIdx.x;
    int lane = tid & 31, wid = tid >> 5;

    for (int i = tid; i < NPT; i += 256) {
        comp[i] = i;
        g_eroot[bm][i] = make_int2(-1, -1);
    }
    if (tid == 0) s_rec = 0;
    __syncthreads();

    int sparse_ok = (g_ovf[bm] == 0);
    int cnt = g_ecnt[bm];
    if (cnt > ECAP) cnt = ECAP;

    for (int phase = 0; phase < 2; phase++) {
        if (phase == 0 && !sparse_ok) continue;
        for (int round = 0; round < 12; round++) {
            if (s_rec >= NPT - 1) break;

            for (int i = tid; i < NPT; i += 256) best[i] = ~0ull;
            __syncthreads();

            if (phase == 0) {
                // sparse scan over filtered edges
                for (int e = tid; e < cnt; e += 256) {
                    u64 k = g_elist[bm][e];
                    int i = (int)((k >> 11) & 2047), j = (int)(k & 2047);
                    int ci = comp[i], cj = comp[j];
                    if (ci != cj) {
                        if (k < best[ci]) atomicMin(&best[ci], k);
                        if (k < best[cj]) atomicMin(&best[cj], k);
                    }
                }
            } else {
                // exact full-matrix scan (fallback; normally never reached)
                const float* Dm = g_D + (size_t)bm * NPT * NPT;
                for (int i = wid; i < NPT; i += 8) {
                    int ci = comp[i];
                    const float4* row = (const float4*)(Dm + (size_t)i * NPT);
                    u64 lb = ~0ull;
                    for (int jc = lane; jc < NPT / 4; jc += 32) {
                        float4 d4 = row[jc];
                        float dv[4] = {d4.x, d4.y, d4.z, d4.w};
#pragma unroll
                        for (int q = 0; q < 4; q++) {
                            int j = jc * 4 + q;
                            if (comp[j] != ci) {
                                int lo = i < j ? i : j, hi = i < j ? j : i;
                                u64 k = ((u64)__float_as_uint(dv[q]) << 22) |
                                        ((unsigned)lo << 11) | (unsigned)hi;
                                if (k < lb) lb = k;
                            }
                        }
                    }
#pragma unroll
                    for (int o = 16; o; o >>= 1) {
                        u64 v = __shfl_down_sync(0xFFFFFFFFu, lb, o);
                        if (v < lb) lb = v;
                    }
                    if (lane == 0 && lb != ~0ull) atomicMin(&best[ci], lb);
                }
            }
            __syncthreads();

            // hook
            for (int c = tid; c < NPT; c += 256) {
                u64 k = best[c];
                int p = c;
                if (k != ~0ull) {
                    int i = (int)((k >> 11) & 2047), j = (int)(k & 2047);
                    int ci = comp[i], cj = comp[j];
                    p = (ci == c) ? cj : ci;
                }
                parent[c] = p;
            }
            __syncthreads();

            // 2-cycle fix (deterministic under the race: either read gives same result)
            for (int c = tid; c < NPT; c += 256) {
                int p = parent[c];
                if (p != c && parent[p] == c && c < p) parent[c] = c;
            }
            __syncthreads();

            // record edges at hooked-root slots
            for (int c = tid; c < NPT; c += 256) {
                if (parent[c] != c) {
                    u64 k = best[c];
                    g_eroot[bm][c] =
                        make_int2((int)((k >> 11) & 2047), (int)(k & 2047));
                    atomicAdd(&s_rec, 1);
                }
            }
            __syncthreads();

            // pointer jumping (double-buffered via best as scratch)
            int* tmp = (int*)best;
            for (int it = 0; it < 11; it++) {
                for (int c = tid; c < NPT; c += 256) tmp[c] = parent[parent[c]];
                __syncthreads();
                for (int c = tid; c < NPT; c += 256) parent[c] = tmp[c];
                __syncthreads();
            }

            // relabel
            for (int i = tid; i < NPT; i += 256) comp[i] = parent[comp[i]];
            __syncthreads();
        }
    }
}

// ---------------------------------------------------------------------------
// 4. loss: 0.5 * sum over all MST edges of (sqrt(D2x) - sqrt(D2z))^2
// ---------------------------------------------------------------------------
__global__ void loss_kernel() {
    int bm = blockIdx.x;
    int b = bm & (BATCH - 1);
    const float* Dx = g_D + (size_t)b * NPT * NPT;
    const float* Dz = g_D + (size_t)(BATCH + b) * NPT * NPT;

    float acc = 0.f;
    for (int s = threadIdx.x; s < NPT; s += 256) {
        int2 p = g_eroot[bm][s];
        if (p.x >= 0) {
            float dx = sqrtf(Dx[(size_t)p.x * NPT + p.y]);
            float dz = sqrtf(Dz[(size_t)p.x * NPT + p.y]);
            float t = dx - dz;
            acc += t * t;
        }
    }
    __shared__ float sm[256];
    sm[threadIdx.x] = acc;
    __syncthreads();
    for (int s = 128; s; s >>= 1) {
        if (threadIdx.x < s) sm[threadIdx.x] += sm[threadIdx.x + s];
        __syncthreads();
    }
    if (threadIdx.x == 0) g_partial[bm] = sm[0];
}

__global__ void final_kernel(float* out) {
    if (threadIdx.x == 0) {
        float s = 0.f;
        for (int i = 0; i < NMAT; i++) s += g_partial[i];
        out[0] = 0.5f * s;
    }
}

// ---------------------------------------------------------------------------
extern "C" void kernel_launch(void* const* d_in, const int* in_sizes, int n_in,
                              void* d_out, int out_size) {
    (void)in_sizes; (void)n_in; (void)out_size;
    const float* gts = (const float*)d_in[0];
    const float* z   = (const float*)d_in[1];

    norms_kernel<<<(NMAT * NPT + 255) / 256, 256>>>(gts, z);

    dim3 g(NPT / 128, NPT / 128, NMAT);
    dist_kernel<<<g, 256>>>(gts, z);

    boruvka_kernel<<<NMAT, 256>>>();

    loss_kernel<<<NMAT, 256>>>();
    final_kernel<<<1, 32>>>((float*)d_out);
}